// round 2
// baseline (speedup 1.0000x reference)
#include <cuda_runtime.h>
#include <math.h>

// ---------------- problem constants ----------------
#define BB    8
#define NN    8192
#define SS    2048
#define KK    32
#define CPTS  64
#define MM    (BB*SS*KK)            // 524288 rows
#define OUT_XYZ_ELEMS (BB*SS*3)     // 49152 floats of new_xyz at front of output

// ---------------- device scratch (no cudaMalloc allowed) ----------------
__device__ int    g_ballidx[MM];
__device__ float  g_x0[(size_t)MM*64];
__device__ float  g_x1[(size_t)MM*64];
__device__ float  g_x2[(size_t)MM*128];
__device__ double g_sum[128];
__device__ double g_sumsq[128];
__device__ float  g_aff_a[128];
__device__ float  g_aff_c[128];

// =====================================================================
// 1) Furthest point sampling: 1 block / batch, 1024 threads, 8 pts/thread.
//    Emits new_xyz directly into d_out (first 49152 floats).
//    Matches XLA semantics: d = fma(dz,dz,fma(dy,dy,dx*dx)),
//    argmax picks FIRST index on ties, first pick is index 0.
// =====================================================================
__global__ void __launch_bounds__(1024,1) k_fps(const float* __restrict__ xyz,
                                                float* __restrict__ out)
{
    int b = blockIdx.x;
    const float* X = xyz + (size_t)b*NN*3;
    int t = threadIdx.x;

    float px[8], py[8], pz[8], md[8];
#pragma unroll
    for (int i=0;i<8;i++){
        int j = i*1024 + t;
        px[i]=X[j*3+0]; py[i]=X[j*3+1]; pz[i]=X[j*3+2];
        md[i]=1e10f;
    }

    __shared__ float s_v[32]; __shared__ int s_i[32];
    __shared__ float s_x[32], s_y[32], s_z[32];
    __shared__ float s_bx, s_by, s_bz; __shared__ int s_bi;

    if (t==0){ s_bx=X[0]; s_by=X[1]; s_bz=X[2]; s_bi=0; }
    __syncthreads();
    float lx=s_bx, ly=s_by, lz=s_bz;

    int lane = t & 31, wid = t >> 5;
    float* onew = out + (size_t)b*SS*3;

    for (int s=0;s<SS;s++){
        if (t==0){
            onew[s*3+0]=lx; onew[s*3+1]=ly; onew[s*3+2]=lz;
        }
        float bv=-1.0f; int bi=0; float bx=0.f,by=0.f,bz=0.f;
#pragma unroll
        for (int i=0;i<8;i++){
            float dx=px[i]-lx, dy=py[i]-ly, dz=pz[i]-lz;
            float d = __fmaf_rn(dz,dz,__fmaf_rn(dy,dy,__fmul_rn(dx,dx)));
            float m = fminf(md[i], d);
            md[i]=m;
            int j = i*1024 + t;
            if (m>bv || (m==bv && j<bi)){ bv=m; bi=j; bx=px[i]; by=py[i]; bz=pz[i]; }
        }
#pragma unroll
        for (int off=16; off>0; off>>=1){
            float ov=__shfl_down_sync(0xffffffffu,bv,off);
            int   oi=__shfl_down_sync(0xffffffffu,bi,off);
            float ox=__shfl_down_sync(0xffffffffu,bx,off);
            float oy=__shfl_down_sync(0xffffffffu,by,off);
            float oz=__shfl_down_sync(0xffffffffu,bz,off);
            if (ov>bv || (ov==bv && oi<bi)){ bv=ov; bi=oi; bx=ox; by=oy; bz=oz; }
        }
        if (lane==0){ s_v[wid]=bv; s_i[wid]=bi; s_x[wid]=bx; s_y[wid]=by; s_z[wid]=bz; }
        __syncthreads();
        if (wid==0){
            bv=s_v[lane]; bi=s_i[lane]; bx=s_x[lane]; by=s_y[lane]; bz=s_z[lane];
#pragma unroll
            for (int off=16; off>0; off>>=1){
                float ov=__shfl_down_sync(0xffffffffu,bv,off);
                int   oi=__shfl_down_sync(0xffffffffu,bi,off);
                float ox=__shfl_down_sync(0xffffffffu,bx,off);
                float oy=__shfl_down_sync(0xffffffffu,by,off);
                float oz=__shfl_down_sync(0xffffffffu,bz,off);
                if (ov>bv || (ov==bv && oi<bi)){ bv=ov; bi=oi; bx=ox; by=oy; bz=oz; }
            }
            if (lane==0){ s_bi=bi; s_bx=bx; s_by=by; s_bz=bz; }
        }
        __syncthreads();
        lx=s_bx; ly=s_by; lz=s_bz;
    }
}

// =====================================================================
// 2) Ball query: warp per centroid, first-K-by-index semantics, pad with first.
//    d2 = qq + pp - 2*dot  (expanded form, matching the reference).
// =====================================================================
__global__ void __launch_bounds__(256,1) k_ballq(const float* __restrict__ xyz,
                                                 const float* __restrict__ newxyz)
{
    extern __shared__ __align__(16) unsigned char s_raw[];
    float4* sp = (float4*)s_raw;   // 8192 * 16B = 128KB

    int b     = blockIdx.x >> 5;        // 32 blocks per batch
    int sbase = (blockIdx.x & 31) * 64; // 64 centroids per block
    const float* X = xyz + (size_t)b*NN*3;

    for (int j=threadIdx.x; j<NN; j+=256){
        float x=X[j*3+0], y=X[j*3+1], z=X[j*3+2];
        float pp=__fmaf_rn(z,z,__fmaf_rn(y,y,__fmul_rn(x,x)));
        sp[j]=make_float4(x,y,z,pp);
    }
    __syncthreads();

    int wid=threadIdx.x>>5, lane=threadIdx.x&31;
    for (int ci=0; ci<8; ci++){
        int s = sbase + wid*8 + ci;
        const float* q = newxyz + ((size_t)b*SS + s)*3;
        float qx=q[0], qy=q[1], qz=q[2];
        float qq=__fmaf_rn(qz,qz,__fmaf_rn(qy,qy,__fmul_rn(qx,qx)));
        int* o = g_ballidx + ((size_t)b*SS + s)*KK;
        int cnt=0, first=0; bool havefirst=false;

        for (int base=0; base<NN; base+=32){
            float4 p = sp[base+lane];
            float dot=__fmaf_rn(qz,p.z,__fmaf_rn(qy,p.y,__fmul_rn(qx,p.x)));
            float d2 =__fmaf_rn(-2.0f,dot,__fadd_rn(qq,p.w));
            bool valid = (d2 <= 0.0625f);
            unsigned m = __ballot_sync(0xffffffffu, valid);
            if (m){
                if (!havefirst){ first = base + (__ffs(m)-1); havefirst=true; }
                int pre = __popc(m & ((1u<<lane)-1u));
                if (valid && (cnt+pre) < KK) o[cnt+pre] = base+lane;
                cnt += __popc(m);
                if (cnt >= KK) break;
            }
        }
        if (cnt < KK){
            for (int p=cnt+lane; p<KK; p+=32) o[p]=first;
        }
    }
}

// =====================================================================
// 3) stats helpers
// =====================================================================
__global__ void k_zero(){
    if (threadIdx.x < 128){ g_sum[threadIdx.x]=0.0; g_sumsq[threadIdx.x]=0.0; }
}

template<int C>
__global__ void __launch_bounds__(256) k_stats(const float* __restrict__ x)
{
    const int G   = 256 / C;
    const int rpb = MM / 1024;
    int tid = threadIdx.x;
    int c  = tid % C;
    int gr = tid / C;
    size_t base = (size_t)blockIdx.x * rpb;
    double s1=0.0, s2=0.0;
    for (int r=gr; r<rpb; r+=G){
        double v = (double)x[(base+r)*(size_t)C + c];
        s1 += v; s2 += v*v;
    }
    __shared__ double sm1[256], sm2[256];
    sm1[tid]=s1; sm2[tid]=s2;
    __syncthreads();
    if (gr==0){
#pragma unroll
        for (int g2=1; g2<G; g2++){ s1+=sm1[tid+g2*C]; s2+=sm2[tid+g2*C]; }
        atomicAdd(&g_sum[c], s1);
        atomicAdd(&g_sumsq[c], s2);
    }
}

__global__ void k_finalize(const float* __restrict__ g, const float* __restrict__ be, int C)
{
    int c = threadIdx.x;
    if (c < C){
        double mean = g_sum[c]   * (1.0/(double)MM);
        double var  = g_sumsq[c] * (1.0/(double)MM) - mean*mean;
        double a = (double)g[c] / sqrt(var + 1e-5);
        g_aff_a[c] = (float)a;
        g_aff_c[c] = (float)((double)be[c] - mean*a);
        g_sum[c]=0.0; g_sumsq[c]=0.0;
    }
}

// =====================================================================
// 4) layer 0: gather (grouped_xyz - center, grouped_pts) + GEMM [M,67]x[67,64]
//    feat stored remapped: cols 0..63 = points, 64..66 = xyz (for alignment);
//    weights remapped identically, so the product is unchanged.
// =====================================================================
__global__ void __launch_bounds__(256) k_layer0(const float* __restrict__ xyz,
                                                const float* __restrict__ pts,
                                                const float* __restrict__ newxyz,
                                                const float* __restrict__ w0,
                                                const float* __restrict__ b0)
{
    __shared__ __align__(16) float sf[64][68];
    __shared__ __align__(16) float sw[67][64];
    int tid = threadIdx.x;

    for (int i=tid; i<67*64; i+=256){
        int o=i/67, c=i%67;
        int cp = (c>=3) ? (c-3) : (64+c);
        sw[cp][o] = w0[i];
    }

    size_t row0 = (size_t)blockIdx.x * 64;
    {
        int r = tid>>2, q = tid&3;
        size_t row = row0 + r;
        int bs = (int)(row >> 5);       // row / K
        int b  = bs >> 11;              // bs / S
        int n  = g_ballidx[row];
        const float4* prow = (const float4*)(pts + ((size_t)b*NN + n)*CPTS);
#pragma unroll
        for (int j=0;j<4;j++){
            float4 v = prow[q*4+j];
            *(float4*)&sf[r][q*16 + j*4] = v;
        }
        if (q==0){
            const float* p3 = xyz + ((size_t)b*NN + n)*3;
            const float* c3 = newxyz + (size_t)bs*3;
            sf[r][64]=p3[0]-c3[0];
            sf[r][65]=p3[1]-c3[1];
            sf[r][66]=p3[2]-c3[2];
        }
    }
    __syncthreads();

    int tx=tid&15, ty=tid>>4;
    float acc[4][4];
#pragma unroll
    for (int i=0;i<4;i++)
#pragma unroll
        for (int j=0;j<4;j++) acc[i][j]=0.f;

#pragma unroll 4
    for (int k=0;k<64;k+=4){
        float av[4][4];
#pragma unroll
        for (int i=0;i<4;i++){
            float4 tv = *(const float4*)&sf[ty*4+i][k];
            av[i][0]=tv.x; av[i][1]=tv.y; av[i][2]=tv.z; av[i][3]=tv.w;
        }
#pragma unroll
        for (int kk=0;kk<4;kk++){
            float4 bv = *(const float4*)&sw[k+kk][tx*4];
#pragma unroll
            for (int i=0;i<4;i++){
                acc[i][0]=fmaf(av[i][kk],bv.x,acc[i][0]);
                acc[i][1]=fmaf(av[i][kk],bv.y,acc[i][1]);
                acc[i][2]=fmaf(av[i][kk],bv.z,acc[i][2]);
                acc[i][3]=fmaf(av[i][kk],bv.w,acc[i][3]);
            }
        }
    }
#pragma unroll
    for (int k=64;k<67;k++){
        float4 bv = *(const float4*)&sw[k][tx*4];
#pragma unroll
        for (int i=0;i<4;i++){
            float a = sf[ty*4+i][k];
            acc[i][0]=fmaf(a,bv.x,acc[i][0]);
            acc[i][1]=fmaf(a,bv.y,acc[i][1]);
            acc[i][2]=fmaf(a,bv.z,acc[i][2]);
            acc[i][3]=fmaf(a,bv.w,acc[i][3]);
        }
    }

    float4 bb = *(const float4*)&b0[tx*4];
#pragma unroll
    for (int i=0;i<4;i++){
        size_t row = row0 + ty*4 + i;
        float4 ov;
        ov.x=acc[i][0]+bb.x; ov.y=acc[i][1]+bb.y;
        ov.z=acc[i][2]+bb.z; ov.w=acc[i][3]+bb.w;
        *(float4*)&g_x0[row*64 + tx*4] = ov;
    }
}

// =====================================================================
// 5) generic layer: y = relu(affine(x_in)) @ W^T + bias   (Cin=64 fixed)
// =====================================================================
template<int COUT>
__global__ void __launch_bounds__(256) k_layerN(const float* __restrict__ xin,
                                                const float* __restrict__ w,
                                                const float* __restrict__ bias,
                                                float* __restrict__ xout)
{
    extern __shared__ __align__(16) unsigned char s_raw[];
    float (*sf)[68]   = (float (*)[68])s_raw;
    float (*sw)[COUT] = (float (*)[COUT])((float*)s_raw + 64*68);
    int tid = threadIdx.x;

    for (int i=tid; i<COUT*64; i+=256){
        int o=i>>6, c=i&63;
        sw[c][o]=w[i];
    }

    size_t row0 = (size_t)blockIdx.x * 64;
    const float4* src = (const float4*)(xin + row0*64);
    for (int i=tid; i<64*16; i+=256){
        int r=i>>4, c=(i&15)*4;
        float4 v = src[i];
        v.x=fmaxf(fmaf(v.x, g_aff_a[c+0], g_aff_c[c+0]), 0.f);
        v.y=fmaxf(fmaf(v.y, g_aff_a[c+1], g_aff_c[c+1]), 0.f);
        v.z=fmaxf(fmaf(v.z, g_aff_a[c+2], g_aff_c[c+2]), 0.f);
        v.w=fmaxf(fmaf(v.w, g_aff_a[c+3], g_aff_c[c+3]), 0.f);
        *(float4*)&sf[r][c] = v;
    }
    __syncthreads();

    constexpr int NC = COUT/16;
    int tx=tid&15, ty=tid>>4;
    float acc[4][NC];
#pragma unroll
    for (int i=0;i<4;i++)
#pragma unroll
        for (int j=0;j<NC;j++) acc[i][j]=0.f;

#pragma unroll 2
    for (int k=0;k<64;k+=4){
        float av[4][4];
#pragma unroll
        for (int i=0;i<4;i++){
            float4 tv = *(const float4*)&sf[ty*4+i][k];
            av[i][0]=tv.x; av[i][1]=tv.y; av[i][2]=tv.z; av[i][3]=tv.w;
        }
#pragma unroll
        for (int kk=0;kk<4;kk++){
            float bv[NC];
#pragma unroll
            for (int j=0;j<NC;j+=4){
                float4 tv = *(const float4*)&sw[k+kk][tx*NC + j];
                bv[j]=tv.x; bv[j+1]=tv.y; bv[j+2]=tv.z; bv[j+3]=tv.w;
            }
#pragma unroll
            for (int i=0;i<4;i++)
#pragma unroll
                for (int j=0;j<NC;j++)
                    acc[i][j]=fmaf(av[i][kk], bv[j], acc[i][j]);
        }
    }

#pragma unroll
    for (int i=0;i<4;i++){
        size_t row = row0 + ty*4 + i;
#pragma unroll
        for (int j=0;j<NC;j+=4){
            int c = tx*NC + j;
            float4 ov;
            ov.x=acc[i][j+0]+bias[c+0];
            ov.y=acc[i][j+1]+bias[c+1];
            ov.z=acc[i][j+2]+bias[c+2];
            ov.w=acc[i][j+3]+bias[c+3];
            *(float4*)&xout[row*COUT + c] = ov;
        }
    }
}

// =====================================================================
// 6) BN+ReLU+maxpool over K and write pooled output
// =====================================================================
__global__ void __launch_bounds__(128) k_pool(float* __restrict__ out)
{
    int bs = blockIdx.x, c = threadIdx.x;
    float a = g_aff_a[c], cc = g_aff_c[c];
    const float* xr = g_x2 + ((size_t)bs*KK)*128 + c;
    float m = 0.0f;   // max over relu(...) >= 0, so 0-init == -inf-init here
#pragma unroll
    for (int k=0;k<KK;k++){
        float v = fmaf(xr[(size_t)k*128], a, cc);
        m = fmaxf(m, v);
    }
    out[OUT_XYZ_ELEMS + (size_t)bs*128 + c] = m;
}

// =====================================================================
// launch
// =====================================================================
extern "C" void kernel_launch(void* const* d_in, const int* in_sizes, int n_in,
                              void* d_out, int out_size)
{
    const float* xyz = (const float*)d_in[0];
    const float* pts = (const float*)d_in[1];
    const float* w0  = (const float*)d_in[2];
    const float* b0  = (const float*)d_in[3];
    const float* g0  = (const float*)d_in[4];
    const float* be0 = (const float*)d_in[5];
    const float* w1  = (const float*)d_in[6];
    const float* b1  = (const float*)d_in[7];
    const float* g1  = (const float*)d_in[8];
    const float* be1 = (const float*)d_in[9];
    const float* w2  = (const float*)d_in[10];
    const float* b2  = (const float*)d_in[11];
    const float* g2  = (const float*)d_in[12];
    const float* be2 = (const float*)d_in[13];
    float* out = (float*)d_out;

    float *px0, *px1, *px2;
    cudaGetSymbolAddress((void**)&px0, g_x0);
    cudaGetSymbolAddress((void**)&px1, g_x1);
    cudaGetSymbolAddress((void**)&px2, g_x2);

    cudaFuncSetAttribute(k_ballq,      cudaFuncAttributeMaxDynamicSharedMemorySize, 131072);
    cudaFuncSetAttribute(k_layerN<64>, cudaFuncAttributeMaxDynamicSharedMemorySize, 33792);
    cudaFuncSetAttribute(k_layerN<128>,cudaFuncAttributeMaxDynamicSharedMemorySize, 50176);

    k_fps  <<<BB, 1024>>>(xyz, out);
    k_ballq<<<BB*(SS/64), 256, 131072>>>(xyz, out);
    k_zero <<<1,128>>>();
    k_layer0<<<MM/64, 256>>>(xyz, pts, out, w0, b0);
    k_stats<64><<<1024,256>>>(px0);
    k_finalize<<<1,128>>>(g0, be0, 64);
    k_layerN<64><<<MM/64, 256, 33792>>>(px0, w1, b1, px1);
    k_stats<64><<<1024,256>>>(px1);
    k_finalize<<<1,128>>>(g1, be1, 64);
    k_layerN<128><<<MM/64, 256, 50176>>>(px1, w2, b2, px2);
    k_stats<128><<<1024,256>>>(px2);
    k_finalize<<<1,128>>>(g2, be2, 128);
    k_pool<<<BB*SS, 128>>>(out);
}

// round 3
// speedup vs baseline: 1.2531x; 1.2531x over previous
#include <cuda_runtime.h>
#include <math.h>

// ---------------- problem constants ----------------
#define BB    8
#define NN    8192
#define SS    2048
#define KK    32
#define CPTS  64
#define MM    (BB*SS*KK)            // 524288 rows
#define OUT_XYZ_ELEMS (BB*SS*3)     // 49152 floats of new_xyz at front of output

// ---------------- device scratch (no cudaMalloc allowed) ----------------
__device__ int    g_ballidx[MM];
__device__ float  g_x0[(size_t)MM*64];
__device__ float  g_x1[(size_t)MM*64];
__device__ float2 g_pool2[(size_t)BB*SS*128];
__device__ double g_sum[128];
__device__ double g_sumsq[128];
__device__ float  g_aff_a[128];
__device__ float  g_aff_c[128];

// ---------------- packed f32x2 helpers (Blackwell) ----------------
__device__ __forceinline__ unsigned long long pack2(float lo, float hi){
    unsigned long long r; asm("mov.b64 %0, {%1, %2};" : "=l"(r) : "f"(lo), "f"(hi)); return r;
}
__device__ __forceinline__ void unpack2(unsigned long long v, float& lo, float& hi){
    asm("mov.b64 {%0, %1}, %2;" : "=f"(lo), "=f"(hi) : "l"(v));
}
__device__ __forceinline__ unsigned long long add2(unsigned long long a, unsigned long long b){
    unsigned long long r; asm("add.rn.f32x2 %0, %1, %2;" : "=l"(r) : "l"(a), "l"(b)); return r;
}
__device__ __forceinline__ unsigned long long mul2(unsigned long long a, unsigned long long b){
    unsigned long long r; asm("mul.rn.f32x2 %0, %1, %2;" : "=l"(r) : "l"(a), "l"(b)); return r;
}
__device__ __forceinline__ unsigned long long fma2(unsigned long long a, unsigned long long b, unsigned long long c){
    unsigned long long r; asm("fma.rn.f32x2 %0, %1, %2, %3;" : "=l"(r) : "l"(a), "l"(b), "l"(c)); return r;
}

// =====================================================================
// 1) Furthest point sampling: 1 block / batch, 1024 threads, 8 pts/thread.
//    Coords held packed (pairs of points) in smem; distances via f32x2
//    (identical per-lane RN rounding). Reduction carries a single u64 key
//    (dist_bits<<32 | ~index): max-key == (max dist, lowest index).
// =====================================================================
__global__ void __launch_bounds__(1024,1) k_fps(const float* __restrict__ xyz,
                                                float* __restrict__ out)
{
    extern __shared__ __align__(16) unsigned char smraw[];
    unsigned long long* sx2  = (unsigned long long*)smraw;   // 4096 entries
    unsigned long long* sy2  = sx2 + 4096;
    unsigned long long* sz2  = sy2 + 4096;
    unsigned long long* skey = sz2 + 4096;                   // 32 entries
    __shared__ int s_bj;

    int b = blockIdx.x;
    const float* X = xyz + (size_t)b*NN*3;
    int t = threadIdx.x, lane = t & 31, wid = t >> 5;

    float md[8];
#pragma unroll
    for (int p=0;p<4;p++){
        int j0 = (2*p)*1024 + t, j1 = j0 + 1024;
        float x0=X[j0*3+0], y0=X[j0*3+1], z0=X[j0*3+2];
        float x1=X[j1*3+0], y1=X[j1*3+1], z1=X[j1*3+2];
        sx2[p*1024+t]=pack2(x0,x1);
        sy2[p*1024+t]=pack2(y0,y1);
        sz2[p*1024+t]=pack2(z0,z1);
        md[2*p]=1e10f; md[2*p+1]=1e10f;
    }
    __syncthreads();

    float lx, ly, lz;
    {
        float hi;
        unpack2(sx2[0], lx, hi);
        unpack2(sy2[0], ly, hi);
        unpack2(sz2[0], lz, hi);
    }

    float* onew = out + (size_t)b*SS*3;

    for (int s=0;s<SS;s++){
        if (t==0){ onew[s*3+0]=lx; onew[s*3+1]=ly; onew[s*3+2]=lz; }
        unsigned long long nlx=pack2(-lx,-lx), nly=pack2(-ly,-ly), nlz=pack2(-lz,-lz);

        float bv=-1.0f; int bj=0;
#pragma unroll
        for (int p=0;p<4;p++){
            unsigned long long dx=add2(sx2[p*1024+t],nlx);
            unsigned long long dy=add2(sy2[p*1024+t],nly);
            unsigned long long dz=add2(sz2[p*1024+t],nlz);
            unsigned long long dd=fma2(dz,dz,fma2(dy,dy,mul2(dx,dx)));
            float d0,d1; unpack2(dd,d0,d1);
            float m0=fminf(md[2*p],d0);   md[2*p]=m0;
            float m1=fminf(md[2*p+1],d1); md[2*p+1]=m1;
            if (m0>bv){ bv=m0; bj=(2*p)*1024+t; }
            if (m1>bv){ bv=m1; bj=(2*p+1)*1024+t; }
        }

        unsigned long long key =
            ((unsigned long long)__float_as_uint(bv)<<32) |
            (unsigned long long)(0xffffffffu - (unsigned)bj);
#pragma unroll
        for (int off=16; off>0; off>>=1){
            unsigned long long o = __shfl_down_sync(0xffffffffu, key, off);
            if (o > key) key = o;
        }
        if (lane==0) skey[wid]=key;
        __syncthreads();
        if (wid==0){
            unsigned long long k2 = skey[lane];
#pragma unroll
            for (int off=16; off>0; off>>=1){
                unsigned long long o = __shfl_down_sync(0xffffffffu, k2, off);
                if (o > k2) k2 = o;
            }
            if (lane==0) s_bj = (int)(0xffffffffu - (unsigned)k2);
        }
        __syncthreads();

        int j = s_bj;
        int i = j >> 10, tt = j & 1023, p = i >> 1, h = i & 1;
        float a0,a1;
        unpack2(sx2[p*1024+tt],a0,a1); lx = h ? a1 : a0;
        unpack2(sy2[p*1024+tt],a0,a1); ly = h ? a1 : a0;
        unpack2(sz2[p*1024+tt],a0,a1); lz = h ? a1 : a0;
    }
}

// =====================================================================
// 2) Ball query: warp per centroid, first-K-by-index semantics, pad with first.
// =====================================================================
__global__ void __launch_bounds__(256,1) k_ballq(const float* __restrict__ xyz,
                                                 const float* __restrict__ newxyz)
{
    extern __shared__ __align__(16) unsigned char s_raw[];
    float4* sp = (float4*)s_raw;   // 8192 * 16B = 128KB

    int b     = blockIdx.x >> 5;
    int sbase = (blockIdx.x & 31) * 64;
    const float* X = xyz + (size_t)b*NN*3;

    for (int j=threadIdx.x; j<NN; j+=256){
        float x=X[j*3+0], y=X[j*3+1], z=X[j*3+2];
        float pp=__fmaf_rn(z,z,__fmaf_rn(y,y,__fmul_rn(x,x)));
        sp[j]=make_float4(x,y,z,pp);
    }
    __syncthreads();

    int wid=threadIdx.x>>5, lane=threadIdx.x&31;
    for (int ci=0; ci<8; ci++){
        int s = sbase + wid*8 + ci;
        const float* q = newxyz + ((size_t)b*SS + s)*3;
        float qx=q[0], qy=q[1], qz=q[2];
        float qq=__fmaf_rn(qz,qz,__fmaf_rn(qy,qy,__fmul_rn(qx,qx)));
        int* o = g_ballidx + ((size_t)b*SS + s)*KK;
        int cnt=0, first=0; bool havefirst=false;

        for (int base=0; base<NN; base+=32){
            float4 p = sp[base+lane];
            float dot=__fmaf_rn(qz,p.z,__fmaf_rn(qy,p.y,__fmul_rn(qx,p.x)));
            float d2 =__fmaf_rn(-2.0f,dot,__fadd_rn(qq,p.w));
            bool valid = (d2 <= 0.0625f);
            unsigned m = __ballot_sync(0xffffffffu, valid);
            if (m){
                if (!havefirst){ first = base + (__ffs(m)-1); havefirst=true; }
                int pre = __popc(m & ((1u<<lane)-1u));
                if (valid && (cnt+pre) < KK) o[cnt+pre] = base+lane;
                cnt += __popc(m);
                if (cnt >= KK) break;
            }
        }
        if (cnt < KK){
            for (int p=cnt+lane; p<KK; p+=32) o[p]=first;
        }
    }
}

// =====================================================================
// 3) stats helpers
// =====================================================================
__global__ void k_zero(){
    if (threadIdx.x < 128){ g_sum[threadIdx.x]=0.0; g_sumsq[threadIdx.x]=0.0; }
}

__global__ void k_finalize(const float* __restrict__ g, const float* __restrict__ be, int C)
{
    int c = threadIdx.x;
    if (c < C){
        double mean = g_sum[c]   * (1.0/(double)MM);
        double var  = g_sumsq[c] * (1.0/(double)MM) - mean*mean;
        double a = (double)g[c] / sqrt(var + 1e-5);
        g_aff_a[c] = (float)a;
        g_aff_c[c] = (float)((double)be[c] - mean*a);
        g_sum[c]=0.0; g_sumsq[c]=0.0;
    }
}

// =====================================================================
// 4) layer 0: gather + GEMM [M,67]x[67,64], stats fused into epilogue
// =====================================================================
__global__ void __launch_bounds__(256) k_layer0(const float* __restrict__ xyz,
                                                const float* __restrict__ pts,
                                                const float* __restrict__ newxyz,
                                                const float* __restrict__ w0,
                                                const float* __restrict__ b0)
{
    __shared__ __align__(16) float sf[64][68];
    __shared__ __align__(16) float sw[67][64];
    int tid = threadIdx.x;

    for (int i=tid; i<67*64; i+=256){
        int o=i/67, c=i%67;
        int cp = (c>=3) ? (c-3) : (64+c);
        sw[cp][o] = w0[i];
    }

    size_t row0 = (size_t)blockIdx.x * 64;
    {
        int r = tid>>2, q = tid&3;
        size_t row = row0 + r;
        int bs = (int)(row >> 5);
        int b  = bs >> 11;
        int n  = g_ballidx[row];
        const float4* prow = (const float4*)(pts + ((size_t)b*NN + n)*CPTS);
#pragma unroll
        for (int j=0;j<4;j++){
            float4 v = prow[q*4+j];
            *(float4*)&sf[r][q*16 + j*4] = v;
        }
        if (q==0){
            const float* p3 = xyz + ((size_t)b*NN + n)*3;
            const float* c3 = newxyz + (size_t)bs*3;
            sf[r][64]=p3[0]-c3[0];
            sf[r][65]=p3[1]-c3[1];
            sf[r][66]=p3[2]-c3[2];
        }
    }
    __syncthreads();

    int tx=tid&15, ty=tid>>4;
    float acc[4][4];
#pragma unroll
    for (int i=0;i<4;i++)
#pragma unroll
        for (int j=0;j<4;j++) acc[i][j]=0.f;

#pragma unroll 4
    for (int k=0;k<64;k+=4){
        float av[4][4];
#pragma unroll
        for (int i=0;i<4;i++){
            float4 tv = *(const float4*)&sf[ty*4+i][k];
            av[i][0]=tv.x; av[i][1]=tv.y; av[i][2]=tv.z; av[i][3]=tv.w;
        }
#pragma unroll
        for (int kk=0;kk<4;kk++){
            float4 bv = *(const float4*)&sw[k+kk][tx*4];
#pragma unroll
            for (int i=0;i<4;i++){
                acc[i][0]=fmaf(av[i][kk],bv.x,acc[i][0]);
                acc[i][1]=fmaf(av[i][kk],bv.y,acc[i][1]);
                acc[i][2]=fmaf(av[i][kk],bv.z,acc[i][2]);
                acc[i][3]=fmaf(av[i][kk],bv.w,acc[i][3]);
            }
        }
    }
#pragma unroll
    for (int k=64;k<67;k++){
        float4 bv = *(const float4*)&sw[k][tx*4];
#pragma unroll
        for (int i=0;i<4;i++){
            float a = sf[ty*4+i][k];
            acc[i][0]=fmaf(a,bv.x,acc[i][0]);
            acc[i][1]=fmaf(a,bv.y,acc[i][1]);
            acc[i][2]=fmaf(a,bv.z,acc[i][2]);
            acc[i][3]=fmaf(a,bv.w,acc[i][3]);
        }
    }

    float4 bb = *(const float4*)&b0[tx*4];
    float s1[4]={0,0,0,0}, s2[4]={0,0,0,0};
#pragma unroll
    for (int i=0;i<4;i++){
        size_t row = row0 + ty*4 + i;
        float4 ov;
        ov.x=acc[i][0]+bb.x; ov.y=acc[i][1]+bb.y;
        ov.z=acc[i][2]+bb.z; ov.w=acc[i][3]+bb.w;
        *(float4*)&g_x0[row*64 + tx*4] = ov;
        s1[0]+=ov.x; s2[0]=fmaf(ov.x,ov.x,s2[0]);
        s1[1]+=ov.y; s2[1]=fmaf(ov.y,ov.y,s2[1]);
        s1[2]+=ov.z; s2[2]=fmaf(ov.z,ov.z,s2[2]);
        s1[3]+=ov.w; s2[3]=fmaf(ov.w,ov.w,s2[3]);
    }

    __syncthreads();
    float2* part = (float2*)&sf[0][0];    // 16x64 float2 = 8KB, fits in sf
#pragma unroll
    for (int j=0;j<4;j++) part[ty*64 + tx*4+j] = make_float2(s1[j], s2[j]);
    __syncthreads();
    if (tid < 64){
        float ss1=0.f, ss2=0.f;
#pragma unroll
        for (int r=0;r<16;r++){ float2 v = part[r*64+tid]; ss1+=v.x; ss2+=v.y; }
        atomicAdd(&g_sum[tid],   (double)ss1);
        atomicAdd(&g_sumsq[tid], (double)ss2);
    }
}

// =====================================================================
// 5) layer 1: y = relu(affine(x0)) @ W^T + bias, Cin=Cout=64, stats fused
// =====================================================================
__global__ void __launch_bounds__(256) k_layer1(const float* __restrict__ xin,
                                                const float* __restrict__ w,
                                                const float* __restrict__ bias,
                                                float* __restrict__ xout)
{
    extern __shared__ __align__(16) unsigned char s_raw[];
    float (*sf)[68] = (float (*)[68])s_raw;
    float (*sw)[64] = (float (*)[64])((float*)s_raw + 64*68);
    int tid = threadIdx.x;

    for (int i=tid; i<64*64; i+=256){
        int o=i>>6, c=i&63;
        sw[c][o]=w[i];
    }

    size_t row0 = (size_t)blockIdx.x * 64;
    const float4* src = (const float4*)(xin + row0*64);
    for (int i=tid; i<64*16; i+=256){
        int r=i>>4, c=(i&15)*4;
        float4 v = src[i];
        v.x=fmaxf(fmaf(v.x, g_aff_a[c+0], g_aff_c[c+0]), 0.f);
        v.y=fmaxf(fmaf(v.y, g_aff_a[c+1], g_aff_c[c+1]), 0.f);
        v.z=fmaxf(fmaf(v.z, g_aff_a[c+2], g_aff_c[c+2]), 0.f);
        v.w=fmaxf(fmaf(v.w, g_aff_a[c+3], g_aff_c[c+3]), 0.f);
        *(float4*)&sf[r][c] = v;
    }
    __syncthreads();

    int tx=tid&15, ty=tid>>4;
    float acc[4][4];
#pragma unroll
    for (int i=0;i<4;i++)
#pragma unroll
        for (int j=0;j<4;j++) acc[i][j]=0.f;

#pragma unroll 4
    for (int k=0;k<64;k+=4){
        float av[4][4];
#pragma unroll
        for (int i=0;i<4;i++){
            float4 tv = *(const float4*)&sf[ty*4+i][k];
            av[i][0]=tv.x; av[i][1]=tv.y; av[i][2]=tv.z; av[i][3]=tv.w;
        }
#pragma unroll
        for (int kk=0;kk<4;kk++){
            float4 bv = *(const float4*)&sw[k+kk][tx*4];
#pragma unroll
            for (int i=0;i<4;i++){
                acc[i][0]=fmaf(av[i][kk],bv.x,acc[i][0]);
                acc[i][1]=fmaf(av[i][kk],bv.y,acc[i][1]);
                acc[i][2]=fmaf(av[i][kk],bv.z,acc[i][2]);
                acc[i][3]=fmaf(av[i][kk],bv.w,acc[i][3]);
            }
        }
    }

    float4 bb = *(const float4*)&bias[tx*4];
    float s1[4]={0,0,0,0}, s2[4]={0,0,0,0};
#pragma unroll
    for (int i=0;i<4;i++){
        size_t row = row0 + ty*4 + i;
        float4 ov;
        ov.x=acc[i][0]+bb.x; ov.y=acc[i][1]+bb.y;
        ov.z=acc[i][2]+bb.z; ov.w=acc[i][3]+bb.w;
        *(float4*)&xout[row*64 + tx*4] = ov;
        s1[0]+=ov.x; s2[0]=fmaf(ov.x,ov.x,s2[0]);
        s1[1]+=ov.y; s2[1]=fmaf(ov.y,ov.y,s2[1]);
        s1[2]+=ov.z; s2[2]=fmaf(ov.z,ov.z,s2[2]);
        s1[3]+=ov.w; s2[3]=fmaf(ov.w,ov.w,s2[3]);
    }

    __syncthreads();
    float2* part = (float2*)s_raw;
#pragma unroll
    for (int j=0;j<4;j++) part[ty*64 + tx*4+j] = make_float2(s1[j], s2[j]);
    __syncthreads();
    if (tid < 64){
        float ss1=0.f, ss2=0.f;
#pragma unroll
        for (int r=0;r<16;r++){ float2 v = part[r*64+tid]; ss1+=v.x; ss2+=v.y; }
        atomicAdd(&g_sum[tid],   (double)ss1);
        atomicAdd(&g_sumsq[tid], (double)ss2);
    }
}

// =====================================================================
// 6) layer 2: y = relu(affine(x1)) @ W^T + bias, Cout=128.
//    x2 is NEVER materialized: per-(b,s) raw max AND min over K plus
//    fused stats are the only outputs.
// =====================================================================
__global__ void __launch_bounds__(256) k_layer2(const float* __restrict__ xin,
                                                const float* __restrict__ w,
                                                const float* __restrict__ bias)
{
    extern __shared__ __align__(16) unsigned char s_raw[];
    float (*sf)[68]  = (float (*)[68])s_raw;
    float (*sw)[128] = (float (*)[128])((float*)s_raw + 64*68);
    int tid = threadIdx.x;

    for (int i=tid; i<128*64; i+=256){
        int o=i>>6, c=i&63;
        sw[c][o]=w[i];
    }

    size_t row0 = (size_t)blockIdx.x * 64;
    const float4* src = (const float4*)(xin + row0*64);
    for (int i=tid; i<64*16; i+=256){
        int r=i>>4, c=(i&15)*4;
        float4 v = src[i];
        v.x=fmaxf(fmaf(v.x, g_aff_a[c+0], g_aff_c[c+0]), 0.f);
        v.y=fmaxf(fmaf(v.y, g_aff_a[c+1], g_aff_c[c+1]), 0.f);
        v.z=fmaxf(fmaf(v.z, g_aff_a[c+2], g_aff_c[c+2]), 0.f);
        v.w=fmaxf(fmaf(v.w, g_aff_a[c+3], g_aff_c[c+3]), 0.f);
        *(float4*)&sf[r][c] = v;
    }
    __syncthreads();

    int tx=tid&15, ty=tid>>4;
    float acc[4][8];
#pragma unroll
    for (int i=0;i<4;i++)
#pragma unroll
        for (int j=0;j<8;j++) acc[i][j]=0.f;

#pragma unroll 2
    for (int k=0;k<64;k+=4){
        float av[4][4];
#pragma unroll
        for (int i=0;i<4;i++){
            float4 tv = *(const float4*)&sf[ty*4+i][k];
            av[i][0]=tv.x; av[i][1]=tv.y; av[i][2]=tv.z; av[i][3]=tv.w;
        }
#pragma unroll
        for (int kk=0;kk<4;kk++){
            float bv[8];
#pragma unroll
            for (int j=0;j<8;j+=4){
                float4 tv = *(const float4*)&sw[k+kk][tx*8 + j];
                bv[j]=tv.x; bv[j+1]=tv.y; bv[j+2]=tv.z; bv[j+3]=tv.w;
            }
#pragma unroll
            for (int i=0;i<4;i++)
#pragma unroll
                for (int j=0;j<8;j++)
                    acc[i][j]=fmaf(av[i][kk], bv[j], acc[i][j]);
        }
    }

    // epilogue: bias, per-thread (sum, sumsq, max, min) per column.
    // thread's 4 rows (ty*4..ty*4+3) all lie in one (b,s) group of 32.
    float s1[8], s2[8], mx[8], mn[8];
#pragma unroll
    for (int j=0;j<8;j++){ s1[j]=0.f; s2[j]=0.f; mx[j]=-3.4e38f; mn[j]=3.4e38f; }
#pragma unroll
    for (int j=0;j<8;j+=4){
        float4 bb = *(const float4*)&bias[tx*8+j];
#pragma unroll
        for (int i=0;i<4;i++){
            float v0=acc[i][j+0]+bb.x, v1=acc[i][j+1]+bb.y;
            float v2=acc[i][j+2]+bb.z, v3=acc[i][j+3]+bb.w;
            s1[j+0]+=v0; s2[j+0]=fmaf(v0,v0,s2[j+0]); mx[j+0]=fmaxf(mx[j+0],v0); mn[j+0]=fminf(mn[j+0],v0);
            s1[j+1]+=v1; s2[j+1]=fmaf(v1,v1,s2[j+1]); mx[j+1]=fmaxf(mx[j+1],v1); mn[j+1]=fminf(mn[j+1],v1);
            s1[j+2]+=v2; s2[j+2]=fmaf(v2,v2,s2[j+2]); mx[j+2]=fmaxf(mx[j+2],v2); mn[j+2]=fminf(mn[j+2],v2);
            s1[j+3]+=v3; s2[j+3]=fmaf(v3,v3,s2[j+3]); mx[j+3]=fmaxf(mx[j+3],v3); mn[j+3]=fminf(mn[j+3],v3);
        }
    }

    __syncthreads();
    float4* part = (float4*)s_raw;       // 16 x 128 float4 = 32KB (fits in 50KB)
#pragma unroll
    for (int j=0;j<8;j++) part[ty*128 + tx*8 + j] = make_float4(s1[j], s2[j], mx[j], mn[j]);
    __syncthreads();

    {   // per-(b,s) max/min over K=32: rows [0,32) -> ty 0..7, rows [32,64) -> ty 8..15
        int g = tid>>7, c = tid&127;
        float gmx=-3.4e38f, gmn=3.4e38f;
#pragma unroll
        for (int r=0;r<8;r++){
            float4 v = part[(g*8+r)*128 + c];
            gmx=fmaxf(gmx, v.z); gmn=fminf(gmn, v.w);
        }
        g_pool2[((size_t)blockIdx.x*2 + g)*128 + c] = make_float2(gmx, gmn);
    }
    if (tid < 128){
        float ss1=0.f, ss2=0.f;
#pragma unroll
        for (int r=0;r<16;r++){ float4 v = part[r*128+tid]; ss1+=v.x; ss2+=v.y; }
        atomicAdd(&g_sum[tid],   (double)ss1);
        atomicAdd(&g_sumsq[tid], (double)ss2);
    }
}

// =====================================================================
// 7) final pool: out = relu(a * rawmax + c)  (a<0 -> use rawmin)
// =====================================================================
__global__ void __launch_bounds__(256) k_pool(float* __restrict__ out)
{
    int idx = blockIdx.x*256 + threadIdx.x;   // over B*S*128
    int c = idx & 127;
    float2 v = g_pool2[idx];
    float a = g_aff_a[c], cc = g_aff_c[c];
    float raw = (a >= 0.f) ? v.x : v.y;
    out[OUT_XYZ_ELEMS + idx] = fmaxf(fmaf(raw, a, cc), 0.f);
}

// =====================================================================
// launch
// =====================================================================
extern "C" void kernel_launch(void* const* d_in, const int* in_sizes, int n_in,
                              void* d_out, int out_size)
{
    const float* xyz = (const float*)d_in[0];
    const float* pts = (const float*)d_in[1];
    const float* w0  = (const float*)d_in[2];
    const float* b0  = (const float*)d_in[3];
    const float* g0  = (const float*)d_in[4];
    const float* be0 = (const float*)d_in[5];
    const float* w1  = (const float*)d_in[6];
    const float* b1  = (const float*)d_in[7];
    const float* g1  = (const float*)d_in[8];
    const float* be1 = (const float*)d_in[9];
    const float* w2  = (const float*)d_in[10];
    const float* b2  = (const float*)d_in[11];
    const float* g2  = (const float*)d_in[12];
    const float* be2 = (const float*)d_in[13];
    float* out = (float*)d_out;

    float *px0, *px1;
    cudaGetSymbolAddress((void**)&px0, g_x0);
    cudaGetSymbolAddress((void**)&px1, g_x1);

    cudaFuncSetAttribute(k_fps,    cudaFuncAttributeMaxDynamicSharedMemorySize, 98560);
    cudaFuncSetAttribute(k_ballq,  cudaFuncAttributeMaxDynamicSharedMemorySize, 131072);
    cudaFuncSetAttribute(k_layer1, cudaFuncAttributeMaxDynamicSharedMemorySize, 33792);
    cudaFuncSetAttribute(k_layer2, cudaFuncAttributeMaxDynamicSharedMemorySize, 50176);

    k_fps  <<<BB, 1024, 98560>>>(xyz, out);
    k_ballq<<<BB*(SS/64), 256, 131072>>>(xyz, out);
    k_zero <<<1,128>>>();
    k_layer0<<<MM/64, 256>>>(xyz, pts, out, w0, b0);
    k_finalize<<<1,128>>>(g0, be0, 64);
    k_layer1<<<MM/64, 256, 33792>>>(px0, w1, b1, px1);
    k_finalize<<<1,128>>>(g1, be1, 64);
    k_layer2<<<MM/64, 256, 50176>>>(px1, w2, b2);
    k_finalize<<<1,128>>>(g2, be2, 128);
    k_pool <<<(BB*SS*128)/256, 256>>>(out);
}

// round 4
// speedup vs baseline: 1.9887x; 1.5870x over previous
#include <cuda_runtime.h>
#include <math.h>

// ---------------- problem constants ----------------
#define BB    8
#define NN    8192
#define SS    2048
#define KK    32
#define CPTS  64
#define MM    (BB*SS*KK)            // 524288 rows
#define OUT_XYZ_ELEMS (BB*SS*3)     // 49152 floats of new_xyz at front of output

typedef unsigned long long u64;

// ---------------- device scratch ----------------
__device__ int    g_ballidx[MM];
__device__ float  g_x0[(size_t)MM*64];
__device__ float  g_x1[(size_t)MM*64];
__device__ float2 g_pool2[(size_t)BB*SS*128];
__device__ double g_sum[128];
__device__ double g_sumsq[128];
__device__ float  g_aff_a[128];
__device__ float  g_aff_c[128];

// ---------------- packed f32x2 helpers ----------------
__device__ __forceinline__ u64 pack2(float lo, float hi){
    u64 r; asm("mov.b64 %0, {%1, %2};" : "=l"(r) : "f"(lo), "f"(hi)); return r;
}
__device__ __forceinline__ u64 dup2(float v){
    u64 r; asm("mov.b64 %0, {%1, %1};" : "=l"(r) : "f"(v)); return r;
}
__device__ __forceinline__ void unpack2(u64 v, float& lo, float& hi){
    asm("mov.b64 {%0, %1}, %2;" : "=f"(lo), "=f"(hi) : "l"(v));
}
__device__ __forceinline__ u64 add2(u64 a, u64 b){
    u64 r; asm("add.rn.f32x2 %0, %1, %2;" : "=l"(r) : "l"(a), "l"(b)); return r;
}
__device__ __forceinline__ u64 mul2(u64 a, u64 b){
    u64 r; asm("mul.rn.f32x2 %0, %1, %2;" : "=l"(r) : "l"(a), "l"(b)); return r;
}
__device__ __forceinline__ u64 fma2(u64 a, u64 b, u64 c){
    u64 r; asm("fma.rn.f32x2 %0, %1, %2, %3;" : "=l"(r) : "l"(a), "l"(b), "l"(c)); return r;
}

// =====================================================================
// 1) FPS: 1 block/batch, 1024 threads, 8 pts/thread in REGISTERS (f32x2).
//    smem coord copy used only for winner-coordinate broadcast lookup.
// =====================================================================
__global__ void __launch_bounds__(1024,1) k_fps(const float* __restrict__ xyz,
                                                float* __restrict__ out)
{
    extern __shared__ __align__(16) unsigned char smraw[];
    u64* sx2  = (u64*)smraw;       // 4096
    u64* sy2  = sx2 + 4096;
    u64* sz2  = sy2 + 4096;
    u64* skey = sz2 + 4096;        // 32
    __shared__ int s_bj;

    int b = blockIdx.x;
    const float* X = xyz + (size_t)b*NN*3;
    int t = threadIdx.x, lane = t & 31, wid = t >> 5;

    u64 cx[4], cy[4], cz[4];
    float md[8];
#pragma unroll
    for (int p=0;p<4;p++){
        int j0 = (2*p)*1024 + t, j1 = j0 + 1024;
        float x0=X[j0*3+0], y0=X[j0*3+1], z0=X[j0*3+2];
        float x1=X[j1*3+0], y1=X[j1*3+1], z1=X[j1*3+2];
        cx[p]=pack2(x0,x1); cy[p]=pack2(y0,y1); cz[p]=pack2(z0,z1);
        sx2[p*1024+t]=cx[p]; sy2[p*1024+t]=cy[p]; sz2[p*1024+t]=cz[p];
        md[2*p]=1e10f; md[2*p+1]=1e10f;
    }
    __syncthreads();

    float lx=X[0], ly=X[1], lz=X[2];
    float* onew = out + (size_t)b*SS*3;

    for (int s=0;s<SS;s++){
        if (t==0){ onew[s*3+0]=lx; onew[s*3+1]=ly; onew[s*3+2]=lz; }
        u64 nlx=dup2(-lx), nly=dup2(-ly), nlz=dup2(-lz);

        float bv=-1.0f;
#pragma unroll
        for (int p=0;p<4;p++){
            u64 dx=add2(cx[p],nlx);
            u64 dy=add2(cy[p],nly);
            u64 dz=add2(cz[p],nlz);
            u64 dd=fma2(dz,dz,fma2(dy,dy,mul2(dx,dx)));
            float d0,d1; unpack2(dd,d0,d1);
            float m0=fminf(md[2*p],d0);   md[2*p]=m0;
            float m1=fminf(md[2*p+1],d1); md[2*p+1]=m1;
            bv=fmaxf(bv,m0); bv=fmaxf(bv,m1);
        }
        // first index whose md equals bv (smallest i wins)
        int bj = 7*1024 + t;
#pragma unroll
        for (int i=6;i>=0;i--) bj = (md[i]==bv) ? (i*1024+t) : bj;

        unsigned bb = __float_as_uint(bv);
        unsigned r  = __reduce_max_sync(0xffffffffu, bb);
        unsigned cand = (bb==r) ? (unsigned)bj : 0xffffffffu;
        unsigned jw = __reduce_min_sync(0xffffffffu, cand);
        if (lane==0) skey[wid] = ((u64)r<<32) | (u64)(0xffffffffu - jw);
        __syncthreads();
        if (wid==0){
            u64 k2 = skey[lane];
#pragma unroll
            for (int off=16; off>0; off>>=1){
                u64 o = __shfl_down_sync(0xffffffffu, k2, off);
                if (o > k2) k2 = o;
            }
            if (lane==0) s_bj = (int)(0xffffffffu - (unsigned)k2);
        }
        __syncthreads();

        int j = s_bj;
        int p = j >> 11, h = (j >> 10) & 1, tt = j & 1023;
        float a0,a1;
        unpack2(sx2[p*1024+tt],a0,a1); lx = h ? a1 : a0;
        unpack2(sy2[p*1024+tt],a0,a1); ly = h ? a1 : a0;
        unpack2(sz2[p*1024+tt],a0,a1); lz = h ? a1 : a0;
    }
}

// =====================================================================
// 2) Ball query (unchanged)
// =====================================================================
__global__ void __launch_bounds__(256,1) k_ballq(const float* __restrict__ xyz,
                                                 const float* __restrict__ newxyz)
{
    extern __shared__ __align__(16) unsigned char s_raw[];
    float4* sp = (float4*)s_raw;

    int b     = blockIdx.x >> 5;
    int sbase = (blockIdx.x & 31) * 64;
    const float* X = xyz + (size_t)b*NN*3;

    for (int j=threadIdx.x; j<NN; j+=256){
        float x=X[j*3+0], y=X[j*3+1], z=X[j*3+2];
        float pp=__fmaf_rn(z,z,__fmaf_rn(y,y,__fmul_rn(x,x)));
        sp[j]=make_float4(x,y,z,pp);
    }
    __syncthreads();

    int wid=threadIdx.x>>5, lane=threadIdx.x&31;
    for (int ci=0; ci<8; ci++){
        int s = sbase + wid*8 + ci;
        const float* q = newxyz + ((size_t)b*SS + s)*3;
        float qx=q[0], qy=q[1], qz=q[2];
        float qq=__fmaf_rn(qz,qz,__fmaf_rn(qy,qy,__fmul_rn(qx,qx)));
        int* o = g_ballidx + ((size_t)b*SS + s)*KK;
        int cnt=0, first=0; bool havefirst=false;

        for (int base=0; base<NN; base+=32){
            float4 p = sp[base+lane];
            float dot=__fmaf_rn(qz,p.z,__fmaf_rn(qy,p.y,__fmul_rn(qx,p.x)));
            float d2 =__fmaf_rn(-2.0f,dot,__fadd_rn(qq,p.w));
            bool valid = (d2 <= 0.0625f);
            unsigned m = __ballot_sync(0xffffffffu, valid);
            if (m){
                if (!havefirst){ first = base + (__ffs(m)-1); havefirst=true; }
                int pre = __popc(m & ((1u<<lane)-1u));
                if (valid && (cnt+pre) < KK) o[cnt+pre] = base+lane;
                cnt += __popc(m);
                if (cnt >= KK) break;
            }
        }
        if (cnt < KK){
            for (int p=cnt+lane; p<KK; p+=32) o[p]=first;
        }
    }
}

// =====================================================================
// 3) stats helpers
// =====================================================================
__global__ void k_zero(){
    if (threadIdx.x < 128){ g_sum[threadIdx.x]=0.0; g_sumsq[threadIdx.x]=0.0; }
}

__global__ void k_finalize(const float* __restrict__ g, const float* __restrict__ be, int C)
{
    int c = threadIdx.x;
    if (c < C){
        double mean = g_sum[c]   * (1.0/(double)MM);
        double var  = g_sumsq[c] * (1.0/(double)MM) - mean*mean;
        double a = (double)g[c] / sqrt(var + 1e-5);
        g_aff_a[c] = (float)a;
        g_aff_c[c] = (float)((double)be[c] - mean*a);
        g_sum[c]=0.0; g_sumsq[c]=0.0;
    }
}

// =====================================================================
// 4) layer 0: gather + GEMM [128 rows x 64 cols], K=67, f32x2 row-pair packed.
//    Channel remap: smem cols 0..63 = points, 64..66 = (xyz - center).
// =====================================================================
__global__ void __launch_bounds__(128) k_layer0(const float* __restrict__ xyz,
                                                const float* __restrict__ pts,
                                                const float* __restrict__ newxyz,
                                                const float* __restrict__ w0,
                                                const float* __restrict__ b0)
{
    extern __shared__ __align__(16) unsigned char s_raw[];
    u64*   sfP = (u64*)s_raw;                       // [67][64] pairs, k-major
    float* sw  = (float*)(s_raw + 67*64*8);         // [67][64] k-major
    int t = threadIdx.x;
    size_t row0 = (size_t)blockIdx.x * 128;

    for (int i=t; i<67*64; i+=128){
        int o = i/67, c = i%67;
        int cp = (c>=3) ? (c-3) : (64+c);
        sw[cp*64+o] = w0[i];
    }
    {
        int p = t & 63, h = t >> 6;
        size_t r0g = row0 + 2*p, r1g = r0g + 1;
        int bs = (int)(r0g >> 5);
        int b  = bs >> 11;
        int n0 = g_ballidx[r0g], n1 = g_ballidx[r1g];
        const float4* ra = (const float4*)(pts + ((size_t)b*NN + n0)*CPTS) + h*8;
        const float4* rb = (const float4*)(pts + ((size_t)b*NN + n1)*CPTS) + h*8;
        int c0 = h*32;
#pragma unroll
        for (int v=0; v<8; v++){
            float4 a = ra[v], b4 = rb[v];
            int c = c0 + v*4;
            sfP[(c+0)*64+p]=pack2(a.x,b4.x);
            sfP[(c+1)*64+p]=pack2(a.y,b4.y);
            sfP[(c+2)*64+p]=pack2(a.z,b4.z);
            sfP[(c+3)*64+p]=pack2(a.w,b4.w);
        }
        if (h==0){
            const float* p3a = xyz + ((size_t)b*NN + n0)*3;
            const float* p3b = xyz + ((size_t)b*NN + n1)*3;
            const float* c3  = newxyz + (size_t)bs*3;
            sfP[64*64+p]=pack2(p3a[0]-c3[0], p3b[0]-c3[0]);
            sfP[65*64+p]=pack2(p3a[1]-c3[1], p3b[1]-c3[1]);
            sfP[66*64+p]=pack2(p3a[2]-c3[2], p3b[2]-c3[2]);
        }
    }
    __syncthreads();

    int tx = t & 7, tp = t >> 3;
    u64 acc[4][8];
#pragma unroll
    for (int i=0;i<4;i++)
#pragma unroll
        for (int j=0;j<8;j++) acc[i][j]=0ull;

    for (int k=0;k<64;k+=4){
#pragma unroll
        for (int kk=0;kk<4;kk++){
            const u64* arow = sfP + (size_t)(k+kk)*64 + tp*4;
            ulonglong2 v0 = *(const ulonglong2*)arow;
            ulonglong2 v1 = *(const ulonglong2*)(arow+2);
            const float4* brow = (const float4*)(sw + (size_t)(k+kk)*64 + tx*8);
            float4 b0v=brow[0], b1v=brow[1];
            u64 bb[8];
            bb[0]=dup2(b0v.x); bb[1]=dup2(b0v.y); bb[2]=dup2(b0v.z); bb[3]=dup2(b0v.w);
            bb[4]=dup2(b1v.x); bb[5]=dup2(b1v.y); bb[6]=dup2(b1v.z); bb[7]=dup2(b1v.w);
            u64 a0=v0.x,a1=v0.y,a2=v1.x,a3=v1.y;
#pragma unroll
            for (int j=0;j<8;j++){
                acc[0][j]=fma2(a0,bb[j],acc[0][j]);
                acc[1][j]=fma2(a1,bb[j],acc[1][j]);
                acc[2][j]=fma2(a2,bb[j],acc[2][j]);
                acc[3][j]=fma2(a3,bb[j],acc[3][j]);
            }
        }
    }
#pragma unroll
    for (int k=64;k<67;k++){
        const u64* arow = sfP + (size_t)k*64 + tp*4;
        ulonglong2 v0 = *(const ulonglong2*)arow;
        ulonglong2 v1 = *(const ulonglong2*)(arow+2);
        const float4* brow = (const float4*)(sw + (size_t)k*64 + tx*8);
        float4 b0v=brow[0], b1v=brow[1];
        u64 bb[8];
        bb[0]=dup2(b0v.x); bb[1]=dup2(b0v.y); bb[2]=dup2(b0v.z); bb[3]=dup2(b0v.w);
        bb[4]=dup2(b1v.x); bb[5]=dup2(b1v.y); bb[6]=dup2(b1v.z); bb[7]=dup2(b1v.w);
        u64 a0=v0.x,a1=v0.y,a2=v1.x,a3=v1.y;
#pragma unroll
        for (int j=0;j<8;j++){
            acc[0][j]=fma2(a0,bb[j],acc[0][j]);
            acc[1][j]=fma2(a1,bb[j],acc[1][j]);
            acc[2][j]=fma2(a2,bb[j],acc[2][j]);
            acc[3][j]=fma2(a3,bb[j],acc[3][j]);
        }
    }

    u64 bP[8];
    {
        float4 b0v = *(const float4*)&b0[tx*8];
        float4 b1v = *(const float4*)&b0[tx*8+4];
        bP[0]=dup2(b0v.x); bP[1]=dup2(b0v.y); bP[2]=dup2(b0v.z); bP[3]=dup2(b0v.w);
        bP[4]=dup2(b1v.x); bP[5]=dup2(b1v.y); bP[6]=dup2(b1v.z); bP[7]=dup2(b1v.w);
    }
    float s1[8], s2[8];
#pragma unroll
    for (int j=0;j<8;j++){ s1[j]=0.f; s2[j]=0.f; }
#pragma unroll
    for (int i=0;i<4;i++){
        size_t ra = row0 + (size_t)(tp*4+i)*2;
        float lo[8], hi[8];
#pragma unroll
        for (int j=0;j<8;j++){
            u64 v = add2(acc[i][j], bP[j]);
            unpack2(v, lo[j], hi[j]);
            s1[j]+=lo[j]; s1[j]+=hi[j];
            s2[j]=fmaf(lo[j],lo[j],s2[j]); s2[j]=fmaf(hi[j],hi[j],s2[j]);
        }
        *(float4*)&g_x0[ra*64 + tx*8]       = make_float4(lo[0],lo[1],lo[2],lo[3]);
        *(float4*)&g_x0[ra*64 + tx*8 + 4]   = make_float4(lo[4],lo[5],lo[6],lo[7]);
        *(float4*)&g_x0[(ra+1)*64 + tx*8]   = make_float4(hi[0],hi[1],hi[2],hi[3]);
        *(float4*)&g_x0[(ra+1)*64 + tx*8+4] = make_float4(hi[4],hi[5],hi[6],hi[7]);
    }
    __syncthreads();
    float2* part = (float2*)s_raw;   // [16][64]
#pragma unroll
    for (int j=0;j<8;j++) part[tp*64 + tx*8 + j] = make_float2(s1[j], s2[j]);
    __syncthreads();
    if (t < 64){
        float ss1=0.f, ss2=0.f;
#pragma unroll
        for (int r=0;r<16;r++){ float2 v = part[r*64+t]; ss1+=v.x; ss2+=v.y; }
        atomicAdd(&g_sum[t],   (double)ss1);
        atomicAdd(&g_sumsq[t], (double)ss2);
    }
}

// =====================================================================
// 5) layer 1: relu(affine(x0)) @ W^T + b, 128x64 tile, f32x2 packed
// =====================================================================
__global__ void __launch_bounds__(128) k_layer1(const float* __restrict__ xin,
                                                const float* __restrict__ w,
                                                const float* __restrict__ bias,
                                                float* __restrict__ xout)
{
    extern __shared__ __align__(16) unsigned char s_raw[];
    u64*   sfP = (u64*)s_raw;                       // [64][64]
    float* sw  = (float*)(s_raw + 64*64*8);         // [64][64]
    int t = threadIdx.x;
    size_t row0 = (size_t)blockIdx.x * 128;

    for (int i=t; i<64*64; i+=128){
        int o=i>>6, c=i&63;
        sw[c*64+o] = w[i];
    }
    {
        int p = t & 63, h = t >> 6;
        const float4* ra = (const float4*)(xin + (row0 + 2*p)*64) + h*8;
        const float4* rb = (const float4*)(xin + (row0 + 2*p+1)*64) + h*8;
        int c0 = h*32;
#pragma unroll
        for (int v=0; v<8; v++){
            float4 a = ra[v], b4 = rb[v];
            int c = c0 + v*4;
            float a0=fmaxf(fmaf(a.x, g_aff_a[c+0], g_aff_c[c+0]),0.f);
            float a1=fmaxf(fmaf(a.y, g_aff_a[c+1], g_aff_c[c+1]),0.f);
            float a2=fmaxf(fmaf(a.z, g_aff_a[c+2], g_aff_c[c+2]),0.f);
            float a3=fmaxf(fmaf(a.w, g_aff_a[c+3], g_aff_c[c+3]),0.f);
            float b0=fmaxf(fmaf(b4.x,g_aff_a[c+0], g_aff_c[c+0]),0.f);
            float b1=fmaxf(fmaf(b4.y,g_aff_a[c+1], g_aff_c[c+1]),0.f);
            float b2=fmaxf(fmaf(b4.z,g_aff_a[c+2], g_aff_c[c+2]),0.f);
            float b3=fmaxf(fmaf(b4.w,g_aff_a[c+3], g_aff_c[c+3]),0.f);
            sfP[(c+0)*64+p]=pack2(a0,b0);
            sfP[(c+1)*64+p]=pack2(a1,b1);
            sfP[(c+2)*64+p]=pack2(a2,b2);
            sfP[(c+3)*64+p]=pack2(a3,b3);
        }
    }
    __syncthreads();

    int tx = t & 7, tp = t >> 3;
    u64 acc[4][8];
#pragma unroll
    for (int i=0;i<4;i++)
#pragma unroll
        for (int j=0;j<8;j++) acc[i][j]=0ull;

    for (int k=0;k<64;k+=4){
#pragma unroll
        for (int kk=0;kk<4;kk++){
            const u64* arow = sfP + (size_t)(k+kk)*64 + tp*4;
            ulonglong2 v0 = *(const ulonglong2*)arow;
            ulonglong2 v1 = *(const ulonglong2*)(arow+2);
            const float4* brow = (const float4*)(sw + (size_t)(k+kk)*64 + tx*8);
            float4 b0v=brow[0], b1v=brow[1];
            u64 bb[8];
            bb[0]=dup2(b0v.x); bb[1]=dup2(b0v.y); bb[2]=dup2(b0v.z); bb[3]=dup2(b0v.w);
            bb[4]=dup2(b1v.x); bb[5]=dup2(b1v.y); bb[6]=dup2(b1v.z); bb[7]=dup2(b1v.w);
            u64 a0=v0.x,a1=v0.y,a2=v1.x,a3=v1.y;
#pragma unroll
            for (int j=0;j<8;j++){
                acc[0][j]=fma2(a0,bb[j],acc[0][j]);
                acc[1][j]=fma2(a1,bb[j],acc[1][j]);
                acc[2][j]=fma2(a2,bb[j],acc[2][j]);
                acc[3][j]=fma2(a3,bb[j],acc[3][j]);
            }
        }
    }

    u64 bP[8];
    {
        float4 b0v = *(const float4*)&bias[tx*8];
        float4 b1v = *(const float4*)&bias[tx*8+4];
        bP[0]=dup2(b0v.x); bP[1]=dup2(b0v.y); bP[2]=dup2(b0v.z); bP[3]=dup2(b0v.w);
        bP[4]=dup2(b1v.x); bP[5]=dup2(b1v.y); bP[6]=dup2(b1v.z); bP[7]=dup2(b1v.w);
    }
    float s1[8], s2[8];
#pragma unroll
    for (int j=0;j<8;j++){ s1[j]=0.f; s2[j]=0.f; }
#pragma unroll
    for (int i=0;i<4;i++){
        size_t ra = row0 + (size_t)(tp*4+i)*2;
        float lo[8], hi[8];
#pragma unroll
        for (int j=0;j<8;j++){
            u64 v = add2(acc[i][j], bP[j]);
            unpack2(v, lo[j], hi[j]);
            s1[j]+=lo[j]; s1[j]+=hi[j];
            s2[j]=fmaf(lo[j],lo[j],s2[j]); s2[j]=fmaf(hi[j],hi[j],s2[j]);
        }
        *(float4*)&xout[ra*64 + tx*8]       = make_float4(lo[0],lo[1],lo[2],lo[3]);
        *(float4*)&xout[ra*64 + tx*8 + 4]   = make_float4(lo[4],lo[5],lo[6],lo[7]);
        *(float4*)&xout[(ra+1)*64 + tx*8]   = make_float4(hi[0],hi[1],hi[2],hi[3]);
        *(float4*)&xout[(ra+1)*64 + tx*8+4] = make_float4(hi[4],hi[5],hi[6],hi[7]);
    }
    __syncthreads();
    float2* part = (float2*)s_raw;
#pragma unroll
    for (int j=0;j<8;j++) part[tp*64 + tx*8 + j] = make_float2(s1[j], s2[j]);
    __syncthreads();
    if (t < 64){
        float ss1=0.f, ss2=0.f;
#pragma unroll
        for (int r=0;r<16;r++){ float2 v = part[r*64+t]; ss1+=v.x; ss2+=v.y; }
        atomicAdd(&g_sum[t],   (double)ss1);
        atomicAdd(&g_sumsq[t], (double)ss2);
    }
}

// =====================================================================
// 6) layer 2: relu(affine(x1)) @ W^T + b, 128x128 tile, f32x2 packed.
//    No x2 materialization: fused stats + per-(b,s) raw max/min over K.
// =====================================================================
__global__ void __launch_bounds__(256) k_layer2(const float* __restrict__ xin,
                                                const float* __restrict__ w,
                                                const float* __restrict__ bias)
{
    extern __shared__ __align__(16) unsigned char s_raw[];
    u64*   sfP = (u64*)s_raw;                       // [64][64]  32KB
    float* sw  = (float*)(s_raw + 64*64*8);         // [64][128] 32KB
    int t = threadIdx.x;
    size_t row0 = (size_t)blockIdx.x * 128;

    for (int i=t; i<128*64; i+=256){
        int o=i>>6, c=i&63;
        sw[c*128+o] = w[i];
    }
    {
        int p = t & 63, q = t >> 6;   // q in 0..3, 16 cols each
        const float4* ra = (const float4*)(xin + (row0 + 2*p)*64) + q*4;
        const float4* rb = (const float4*)(xin + (row0 + 2*p+1)*64) + q*4;
        int c0 = q*16;
#pragma unroll
        for (int v=0; v<4; v++){
            float4 a = ra[v], b4 = rb[v];
            int c = c0 + v*4;
            float a0=fmaxf(fmaf(a.x, g_aff_a[c+0], g_aff_c[c+0]),0.f);
            float a1=fmaxf(fmaf(a.y, g_aff_a[c+1], g_aff_c[c+1]),0.f);
            float a2=fmaxf(fmaf(a.z, g_aff_a[c+2], g_aff_c[c+2]),0.f);
            float a3=fmaxf(fmaf(a.w, g_aff_a[c+3], g_aff_c[c+3]),0.f);
            float b0=fmaxf(fmaf(b4.x,g_aff_a[c+0], g_aff_c[c+0]),0.f);
            float b1=fmaxf(fmaf(b4.y,g_aff_a[c+1], g_aff_c[c+1]),0.f);
            float b2=fmaxf(fmaf(b4.z,g_aff_a[c+2], g_aff_c[c+2]),0.f);
            float b3=fmaxf(fmaf(b4.w,g_aff_a[c+3], g_aff_c[c+3]),0.f);
            sfP[(c+0)*64+p]=pack2(a0,b0);
            sfP[(c+1)*64+p]=pack2(a1,b1);
            sfP[(c+2)*64+p]=pack2(a2,b2);
            sfP[(c+3)*64+p]=pack2(a3,b3);
        }
    }
    __syncthreads();

    int tx = t & 15, tp = t >> 4;
    u64 acc[4][8];
#pragma unroll
    for (int i=0;i<4;i++)
#pragma unroll
        for (int j=0;j<8;j++) acc[i][j]=0ull;

    for (int k=0;k<64;k+=4){
#pragma unroll
        for (int kk=0;kk<4;kk++){
            const u64* arow = sfP + (size_t)(k+kk)*64 + tp*4;
            ulonglong2 v0 = *(const ulonglong2*)arow;
            ulonglong2 v1 = *(const ulonglong2*)(arow+2);
            const float4* brow = (const float4*)(sw + (size_t)(k+kk)*128 + tx*8);
            float4 b0v=brow[0], b1v=brow[1];
            u64 bb[8];
            bb[0]=dup2(b0v.x); bb[1]=dup2(b0v.y); bb[2]=dup2(b0v.z); bb[3]=dup2(b0v.w);
            bb[4]=dup2(b1v.x); bb[5]=dup2(b1v.y); bb[6]=dup2(b1v.z); bb[7]=dup2(b1v.w);
            u64 a0=v0.x,a1=v0.y,a2=v1.x,a3=v1.y;
#pragma unroll
            for (int j=0;j<8;j++){
                acc[0][j]=fma2(a0,bb[j],acc[0][j]);
                acc[1][j]=fma2(a1,bb[j],acc[1][j]);
                acc[2][j]=fma2(a2,bb[j],acc[2][j]);
                acc[3][j]=fma2(a3,bb[j],acc[3][j]);
            }
        }
    }

    u64 bP[8];
    {
        float4 b0v = *(const float4*)&bias[tx*8];
        float4 b1v = *(const float4*)&bias[tx*8+4];
        bP[0]=dup2(b0v.x); bP[1]=dup2(b0v.y); bP[2]=dup2(b0v.z); bP[3]=dup2(b0v.w);
        bP[4]=dup2(b1v.x); bP[5]=dup2(b1v.y); bP[6]=dup2(b1v.z); bP[7]=dup2(b1v.w);
    }
    float s1[8], s2[8], mx[8], mn[8];
#pragma unroll
    for (int j=0;j<8;j++){ s1[j]=0.f; s2[j]=0.f; mx[j]=-3.4e38f; mn[j]=3.4e38f; }
#pragma unroll
    for (int i=0;i<4;i++){
#pragma unroll
        for (int j=0;j<8;j++){
            u64 v = add2(acc[i][j], bP[j]);
            float lo, hi; unpack2(v, lo, hi);
            s1[j]+=lo; s1[j]+=hi;
            s2[j]=fmaf(lo,lo,s2[j]); s2[j]=fmaf(hi,hi,s2[j]);
            mx[j]=fmaxf(mx[j], fmaxf(lo,hi));
            mn[j]=fminf(mn[j], fminf(lo,hi));
        }
    }
    __syncthreads();
    float4* part = (float4*)s_raw;   // [16][128] = 32KB
#pragma unroll
    for (int j=0;j<8;j++) part[tp*128 + tx*8 + j] = make_float4(s1[j], s2[j], mx[j], mn[j]);
    __syncthreads();

    for (int u=t; u<512; u+=256){
        int g = u >> 7, c = u & 127;
        float gmx=-3.4e38f, gmn=3.4e38f;
#pragma unroll
        for (int r=0;r<4;r++){
            float4 v = part[(g*4+r)*128 + c];
            gmx=fmaxf(gmx, v.z); gmn=fminf(gmn, v.w);
        }
        g_pool2[((size_t)blockIdx.x*4 + g)*128 + c] = make_float2(gmx, gmn);
    }
    if (t < 128){
        float ss1=0.f, ss2=0.f;
#pragma unroll
        for (int r=0;r<16;r++){ float4 v = part[r*128+t]; ss1+=v.x; ss2+=v.y; }
        atomicAdd(&g_sum[t],   (double)ss1);
        atomicAdd(&g_sumsq[t], (double)ss2);
    }
}

// =====================================================================
// 7) final pool: out = relu(a * rawmax + c)  (a<0 -> rawmin)
// =====================================================================
__global__ void __launch_bounds__(256) k_pool(float* __restrict__ out)
{
    int idx = blockIdx.x*256 + threadIdx.x;
    int c = idx & 127;
    float2 v = g_pool2[idx];
    float a = g_aff_a[c], cc = g_aff_c[c];
    float raw = (a >= 0.f) ? v.x : v.y;
    out[OUT_XYZ_ELEMS + idx] = fmaxf(fmaf(raw, a, cc), 0.f);
}

// =====================================================================
// launch
// =====================================================================
extern "C" void kernel_launch(void* const* d_in, const int* in_sizes, int n_in,
                              void* d_out, int out_size)
{
    const float* xyz = (const float*)d_in[0];
    const float* pts = (const float*)d_in[1];
    const float* w0  = (const float*)d_in[2];
    const float* b0  = (const float*)d_in[3];
    const float* g0  = (const float*)d_in[4];
    const float* be0 = (const float*)d_in[5];
    const float* w1  = (const float*)d_in[6];
    const float* b1  = (const float*)d_in[7];
    const float* g1  = (const float*)d_in[8];
    const float* be1 = (const float*)d_in[9];
    const float* w2  = (const float*)d_in[10];
    const float* b2  = (const float*)d_in[11];
    const float* g2  = (const float*)d_in[12];
    const float* be2 = (const float*)d_in[13];
    float* out = (float*)d_out;

    float *px0, *px1;
    cudaGetSymbolAddress((void**)&px0, g_x0);
    cudaGetSymbolAddress((void**)&px1, g_x1);

    cudaFuncSetAttribute(k_fps,    cudaFuncAttributeMaxDynamicSharedMemorySize, 98560);
    cudaFuncSetAttribute(k_ballq,  cudaFuncAttributeMaxDynamicSharedMemorySize, 131072);
    cudaFuncSetAttribute(k_layer0, cudaFuncAttributeMaxDynamicSharedMemorySize, 51456);
    cudaFuncSetAttribute(k_layer1, cudaFuncAttributeMaxDynamicSharedMemorySize, 49152);
    cudaFuncSetAttribute(k_layer2, cudaFuncAttributeMaxDynamicSharedMemorySize, 65536);

    k_fps  <<<BB, 1024, 98560>>>(xyz, out);
    k_ballq<<<BB*(SS/64), 256, 131072>>>(xyz, out);
    k_zero <<<1,128>>>();
    k_layer0<<<MM/128, 128, 51456>>>(xyz, pts, out, w0, b0);
    k_finalize<<<1,128>>>(g0, be0, 64);
    k_layer1<<<MM/128, 128, 49152>>>(px0, w1, b1, px1);
    k_finalize<<<1,128>>>(g1, be1, 64);
    k_layer2<<<MM/128, 256, 65536>>>(px1, w2, b2);
    k_finalize<<<1,128>>>(g2, be2, 128);
    k_pool <<<(BB*SS*128)/256, 256>>>(out);
}